// round 10
// baseline (speedup 1.0000x reference)
#include <cuda_runtime.h>
#include <cuda_fp16.h>

// ---------------- static scratch ----------------
#define N_MAX 50000
#define E_MAX 800000
#define ET_MAX (N_MAX + E_MAX)

__device__ __align__(16) float g_bufA[(size_t)N_MAX * 128];
__device__ __align__(16) float g_bufB[(size_t)N_MAX * 128];
__device__ __align__(16) float g_bufC[(size_t)N_MAX * 64];
__device__ __align__(16) unsigned g_h16[(size_t)N_MAX * 64];  // fp16x2 feature cache
__device__ __align__(16) float g_es[N_MAX * 4];
__device__ __align__(16) float g_ed[N_MAX * 4];
__device__ int   g_srcv[ET_MAX];
__device__ int   g_dstv[ET_MAX];
__device__ int   g_csr[ET_MAX];
__device__ int   g_cnt[N_MAX];
__device__ int   g_fill[N_MAX];
__device__ int   g_rowoff[N_MAX + 1];
__device__ int   g_blksum[512];
__device__ __align__(16) float g_sg1[64];
__device__ __align__(16) float g_sg2[128];
__device__ int   g_is64;

__device__ __forceinline__ float* pick(int sel, float* ext) {
    switch (sel) {
        case 0: return g_bufA;
        case 1: return g_bufB;
        case 2: return g_bufC;
        default: return ext;
    }
}

__device__ __forceinline__ const float* pick_scale(int sel) {
    switch (sel) {
        case 0: return g_sg1;
        case 1: return g_sg2;
        default: return nullptr;
    }
}

__device__ __forceinline__ float lrelu(float x) { return x > 0.f ? x : 0.2f * x; }

__device__ __forceinline__ unsigned f2tf32(float x) {
    unsigned u;
    asm("cvt.rna.tf32.f32 %0, %1;" : "=r"(u) : "f"(x));
    return u;
}

__device__ __forceinline__ void mma_tf32(float* d, const unsigned* a, const unsigned* b) {
    asm volatile(
        "mma.sync.aligned.m16n8k8.row.col.f32.tf32.tf32.f32 "
        "{%0,%1,%2,%3}, {%4,%5,%6,%7}, {%8,%9}, {%0,%1,%2,%3};\n"
        : "+f"(d[0]), "+f"(d[1]), "+f"(d[2]), "+f"(d[3])
        : "r"(a[0]), "r"(a[1]), "r"(a[2]), "r"(a[3]), "r"(b[0]), "r"(b[1]));
}

// ---------------- fused zero + dtype sniff ----------------
__global__ void zero_detect_kernel(const int* __restrict__ ei32, int N) {
    int i = blockIdx.x * blockDim.x + threadIdx.x;
    if (i < N) { g_cnt[i] = 0; g_fill[i] = 0; }
    if (blockIdx.x == 0 && threadIdx.x < 32) {
        int lane = threadIdx.x;
        int zeros = 0;
        for (int k = lane; k < 128; k += 32)
            if (ei32[2 * k + 1] == 0) zeros++;
        #pragma unroll
        for (int o = 16; o; o >>= 1) zeros += __shfl_xor_sync(0xffffffffu, zeros, o);
        if (lane == 0) g_is64 = (zeros > 64) ? 1 : 0;
    }
}

__global__ void build_edges_kernel(const void* __restrict__ ei, int E, int N) {
    int i = blockIdx.x * blockDim.x + threadIdx.x;
    int tot = E + N;
    if (i >= tot) return;
    int s, d;
    if (i < E) {
        if (g_is64) {
            const long long* p = (const long long*)ei;
            s = (int)p[i]; d = (int)p[(size_t)E + i];
        } else {
            const int* p = (const int*)ei;
            s = p[i]; d = p[E + i];
        }
        s = min(max(s, 0), N - 1);
        d = min(max(d, 0), N - 1);
    } else {
        s = i - E; d = s;
    }
    g_srcv[i] = s;
    g_dstv[i] = d;
    atomicAdd(&g_cnt[d], 1);
}

// ---------------- parallel 3-phase exclusive scan ----------------
__global__ void scan_reduce_kernel(int N) {
    __shared__ int ws[8];
    int b = blockIdx.x;
    int i = b * 256 + threadIdx.x;
    int v = (i < N) ? g_cnt[i] : 0;
    #pragma unroll
    for (int o = 16; o; o >>= 1) v += __shfl_xor_sync(0xffffffffu, v, o);
    int lane = threadIdx.x & 31, wid = threadIdx.x >> 5;
    if (lane == 0) ws[wid] = v;
    __syncthreads();
    if (threadIdx.x < 8) {
        int s = ws[threadIdx.x];
        #pragma unroll
        for (int o = 4; o; o >>= 1) s += __shfl_xor_sync(0xffu, s, o);
        if (threadIdx.x == 0) g_blksum[b] = s;
    }
}

__global__ void scan_block_kernel(int nblk, const float* __restrict__ ga,
                                  const float* __restrict__ gb) {
    __shared__ int wsum[16];
    int tid = threadIdx.x;
    int lane = tid & 31, wid = tid >> 5;
    int v = (tid < nblk) ? g_blksum[tid] : 0;
    int x = v;
    #pragma unroll
    for (int o = 1; o < 32; o <<= 1) {
        int y = __shfl_up_sync(0xffffffffu, x, o);
        if (lane >= o) x += y;
    }
    if (lane == 31) wsum[wid] = x;
    __syncthreads();
    if (tid < 16) {
        int ws = wsum[tid];
        int xs = ws;
        #pragma unroll
        for (int o = 1; o < 16; o <<= 1) {
            int y = __shfl_up_sync(0xffffu, xs, o);
            if (tid >= o) xs += y;
        }
        wsum[tid] = xs - ws;
    }
    __syncthreads();
    if (tid < nblk) g_blksum[tid] = wsum[wid] + x - v;
    float r = rsqrtf(1.0f + 1e-5f);
    if (tid < 64)  g_sg1[tid] = ga[tid] * r;
    if (tid < 128) g_sg2[tid] = gb[tid] * r;
}

__global__ void scan_final_kernel(int N) {
    __shared__ int wsum[8];
    int b = blockIdx.x;
    int tid = threadIdx.x;
    int lane = tid & 31, wid = tid >> 5;
    int i = b * 256 + tid;
    int v = (i < N) ? g_cnt[i] : 0;
    int x = v;
    #pragma unroll
    for (int o = 1; o < 32; o <<= 1) {
        int y = __shfl_up_sync(0xffffffffu, x, o);
        if (lane >= o) x += y;
    }
    if (lane == 31) wsum[wid] = x;
    __syncthreads();
    if (tid < 8) {
        int ws = wsum[tid];
        int xs = ws;
        #pragma unroll
        for (int o = 1; o < 8; o <<= 1) {
            int y = __shfl_up_sync(0xffu, xs, o);
            if (tid >= o) xs += y;
        }
        wsum[tid] = xs - ws;
    }
    __syncthreads();
    int excl = g_blksum[b] + wsum[wid] + x - v;
    if (i < N) g_rowoff[i] = excl;
    if (i == N - 1) g_rowoff[N] = excl + v;
}

__global__ void scatter_kernel(int ET) {
    int i = blockIdx.x * blockDim.x + threadIdx.x;
    if (i >= ET) return;
    int d = g_dstv[i];
    int pos = g_rowoff[d] + atomicAdd(&g_fill[d], 1);
    g_csr[pos] = g_srcv[i];
}

// ---------------- tf32 GEMM, tile 128x128 (M must be 128) ----------------
__global__ void __launch_bounds__(256)
gemm_tc128_kernel(const float* __restrict__ Aext, int Asel,
                  const float* __restrict__ B,
                  const float* __restrict__ bias,
                  int ssel, const float* __restrict__ shift,
                  float* __restrict__ Cext, int Csel,
                  int N, int K, int do_relu) {
    const int M = 128;
    const float* A = pick(Asel, (float*)Aext);
    float* C = pick(Csel, Cext);
    const float* scale = pick_scale(ssel);

    __shared__ unsigned sA[128][36];
    __shared__ unsigned sB[32][132];

    int row0 = blockIdx.x * 128;
    int tid = threadIdx.x;
    int lane = tid & 31;
    int warp = tid >> 5;
    int wm = warp >> 2, wn = warp & 3;

    float acc[4][4][4];
    #pragma unroll
    for (int i = 0; i < 4; i++)
        #pragma unroll
        for (int j = 0; j < 4; j++)
            #pragma unroll
            for (int q = 0; q < 4; q++) acc[i][j][q] = 0.f;

    int ar[4], ac4[4], bkr[4], bc4[4];
    #pragma unroll
    for (int l = 0; l < 4; l++) {
        int fi = tid + l * 256;
        ar[l]  = fi >> 3;
        ac4[l] = (fi & 7) << 2;
        bkr[l] = fi >> 5;
        bc4[l] = (fi & 31) << 2;
    }

    float4 pa[4], pb[4];
    #pragma unroll
    for (int l = 0; l < 4; l++) {
        pa[l] = make_float4(0.f, 0.f, 0.f, 0.f);
        if (row0 + ar[l] < N)
            pa[l] = *reinterpret_cast<const float4*>(A + (size_t)(row0 + ar[l]) * K + ac4[l]);
        pb[l] = *reinterpret_cast<const float4*>(B + (size_t)bkr[l] * M + bc4[l]);
    }

    for (int k0 = 0; k0 < K; k0 += 32) {
        #pragma unroll
        for (int l = 0; l < 4; l++) {
            sA[ar[l]][ac4[l] + 0] = f2tf32(pa[l].x);
            sA[ar[l]][ac4[l] + 1] = f2tf32(pa[l].y);
            sA[ar[l]][ac4[l] + 2] = f2tf32(pa[l].z);
            sA[ar[l]][ac4[l] + 3] = f2tf32(pa[l].w);
            sB[bkr[l]][bc4[l] + 0] = f2tf32(pb[l].x);
            sB[bkr[l]][bc4[l] + 1] = f2tf32(pb[l].y);
            sB[bkr[l]][bc4[l] + 2] = f2tf32(pb[l].z);
            sB[bkr[l]][bc4[l] + 3] = f2tf32(pb[l].w);
        }
        __syncthreads();

        int kn = k0 + 32;
        if (kn < K) {
            #pragma unroll
            for (int l = 0; l < 4; l++) {
                pa[l] = make_float4(0.f, 0.f, 0.f, 0.f);
                if (row0 + ar[l] < N)
                    pa[l] = *reinterpret_cast<const float4*>(A + (size_t)(row0 + ar[l]) * K + kn + ac4[l]);
                pb[l] = *reinterpret_cast<const float4*>(B + (size_t)(kn + bkr[l]) * M + bc4[l]);
            }
        }

        #pragma unroll
        for (int ks = 0; ks < 4; ks++) {
            int kk = ks * 8;
            unsigned af[4][4];
            #pragma unroll
            for (int i = 0; i < 4; i++) {
                int r0 = wm * 64 + i * 16 + (lane >> 2);
                int c0 = kk + (lane & 3);
                af[i][0] = sA[r0][c0];
                af[i][1] = sA[r0 + 8][c0];
                af[i][2] = sA[r0][c0 + 4];
                af[i][3] = sA[r0 + 8][c0 + 4];
            }
            unsigned bf[4][2];
            #pragma unroll
            for (int j = 0; j < 4; j++) {
                int c = wn * 32 + j * 8 + (lane >> 2);
                int kr = kk + (lane & 3);
                bf[j][0] = sB[kr][c];
                bf[j][1] = sB[kr + 4][c];
            }
            #pragma unroll
            for (int i = 0; i < 4; i++)
                #pragma unroll
                for (int j = 0; j < 4; j++)
                    mma_tf32(acc[i][j], af[i], bf[j]);
        }
        __syncthreads();
    }

    #pragma unroll
    for (int i = 0; i < 4; i++) {
        int r0 = row0 + wm * 64 + i * 16 + (lane >> 2);
        #pragma unroll
        for (int j = 0; j < 4; j++) {
            int c0 = wn * 32 + j * 8 + ((lane & 3) << 1);
            #pragma unroll
            for (int q = 0; q < 4; q++) {
                int r = r0 + (q >> 1) * 8;
                int c = c0 + (q & 1);
                if (r >= N) continue;
                float v = acc[i][j][q];
                if (bias)  v += bias[c];
                if (do_relu) v = fmaxf(v, 0.f);
                if (scale) v = v * scale[c] + shift[c];
                C[(size_t)r * M + c] = v;
            }
        }
    }
}

// ---------------- tf32 GEMM, tile 128x64 (used for M=64) ----------------
__global__ void __launch_bounds__(256)
gemm_tc64_kernel(const float* __restrict__ Aext, int Asel,
                 const float* __restrict__ B,
                 const float* __restrict__ bias,
                 int ssel, const float* __restrict__ shift,
                 float* __restrict__ Cext, int Csel,
                 int N, int K, int M, int do_relu) {
    const float* A = pick(Asel, (float*)Aext);
    float* C = pick(Csel, Cext);
    const float* scale = pick_scale(ssel);

    __shared__ unsigned sA[128][36];
    __shared__ unsigned sB[32][68];

    int row0 = blockIdx.x * 128;
    int col0 = blockIdx.y * 64;
    int tid = threadIdx.x;
    int lane = tid & 31;
    int warp = tid >> 5;
    int wm = warp >> 1, wn = warp & 1;

    float acc[2][4][4];
    #pragma unroll
    for (int i = 0; i < 2; i++)
        #pragma unroll
        for (int j = 0; j < 4; j++)
            #pragma unroll
            for (int q = 0; q < 4; q++) acc[i][j][q] = 0.f;

    int ar[4], ac4[4];
    #pragma unroll
    for (int l = 0; l < 4; l++) {
        int fi = tid + l * 256;
        ar[l] = fi >> 3;
        ac4[l] = (fi & 7) << 2;
    }
    int bkr[2], bc4[2];
    #pragma unroll
    for (int l = 0; l < 2; l++) {
        int fi = tid + l * 256;
        bkr[l] = fi >> 4;
        bc4[l] = (fi & 15) << 2;
    }

    float4 pa[4], pb[2];
    #pragma unroll
    for (int l = 0; l < 4; l++) {
        pa[l] = make_float4(0.f, 0.f, 0.f, 0.f);
        if (row0 + ar[l] < N)
            pa[l] = *reinterpret_cast<const float4*>(A + (size_t)(row0 + ar[l]) * K + ac4[l]);
    }
    #pragma unroll
    for (int l = 0; l < 2; l++)
        pb[l] = *reinterpret_cast<const float4*>(B + (size_t)bkr[l] * M + col0 + bc4[l]);

    for (int k0 = 0; k0 < K; k0 += 32) {
        #pragma unroll
        for (int l = 0; l < 4; l++) {
            sA[ar[l]][ac4[l] + 0] = f2tf32(pa[l].x);
            sA[ar[l]][ac4[l] + 1] = f2tf32(pa[l].y);
            sA[ar[l]][ac4[l] + 2] = f2tf32(pa[l].z);
            sA[ar[l]][ac4[l] + 3] = f2tf32(pa[l].w);
        }
        #pragma unroll
        for (int l = 0; l < 2; l++) {
            sB[bkr[l]][bc4[l] + 0] = f2tf32(pb[l].x);
            sB[bkr[l]][bc4[l] + 1] = f2tf32(pb[l].y);
            sB[bkr[l]][bc4[l] + 2] = f2tf32(pb[l].z);
            sB[bkr[l]][bc4[l] + 3] = f2tf32(pb[l].w);
        }
        __syncthreads();

        int kn = k0 + 32;
        if (kn < K) {
            #pragma unroll
            for (int l = 0; l < 4; l++) {
                pa[l] = make_float4(0.f, 0.f, 0.f, 0.f);
                if (row0 + ar[l] < N)
                    pa[l] = *reinterpret_cast<const float4*>(A + (size_t)(row0 + ar[l]) * K + kn + ac4[l]);
            }
            #pragma unroll
            for (int l = 0; l < 2; l++)
                pb[l] = *reinterpret_cast<const float4*>(B + (size_t)(kn + bkr[l]) * M + col0 + bc4[l]);
        }

        #pragma unroll
        for (int ks = 0; ks < 4; ks++) {
            int kk = ks * 8;
            unsigned af[2][4];
            #pragma unroll
            for (int i = 0; i < 2; i++) {
                int r0 = wm * 32 + i * 16 + (lane >> 2);
                int c0 = kk + (lane & 3);
                af[i][0] = sA[r0][c0];
                af[i][1] = sA[r0 + 8][c0];
                af[i][2] = sA[r0][c0 + 4];
                af[i][3] = sA[r0 + 8][c0 + 4];
            }
            unsigned bf[4][2];
            #pragma unroll
            for (int j = 0; j < 4; j++) {
                int c = wn * 32 + j * 8 + (lane >> 2);
                int kr = kk + (lane & 3);
                bf[j][0] = sB[kr][c];
                bf[j][1] = sB[kr + 4][c];
            }
            #pragma unroll
            for (int i = 0; i < 2; i++)
                #pragma unroll
                for (int j = 0; j < 4; j++)
                    mma_tf32(acc[i][j], af[i], bf[j]);
        }
        __syncthreads();
    }

    #pragma unroll
    for (int i = 0; i < 2; i++) {
        int r0 = row0 + wm * 32 + i * 16 + (lane >> 2);
        #pragma unroll
        for (int j = 0; j < 4; j++) {
            int c0 = col0 + wn * 32 + j * 8 + ((lane & 3) << 1);
            #pragma unroll
            for (int q = 0; q < 4; q++) {
                int r = r0 + (q >> 1) * 8;
                int c = c0 + (q & 1);
                if (r >= N) continue;
                float v = acc[i][j][q];
                if (bias)  v += bias[c];
                if (do_relu) v = fmaxf(v, 0.f);
                if (scale) v = v * scale[c] + shift[c];
                C[(size_t)r * M + c] = v;
            }
        }
    }
}

// ---------------- attention scores + fp16 feature cache ----------------
// thread = (node, head): dot products vs a_src/a_dst AND write 32 feats as fp16
__global__ void scores_kernel(int hsel,
                              const float* __restrict__ as, const float* __restrict__ ad,
                              int N) {
    const float* h = pick(hsel, nullptr);
    int idx = blockIdx.x * blockDim.x + threadIdx.x;
    int n = idx >> 2, hh = idx & 3;
    if (n >= N) return;
    const float4* hp = reinterpret_cast<const float4*>(h + (size_t)n * 128 + hh * 32);
    const float4* ap = reinterpret_cast<const float4*>(as + hh * 32);
    const float4* bp = reinterpret_cast<const float4*>(ad + hh * 32);
    __half2* o = reinterpret_cast<__half2*>(g_h16) + (size_t)n * 64 + hh * 16;
    float s = 0.f, d = 0.f;
    #pragma unroll
    for (int i = 0; i < 8; i++) {
        float4 hv = hp[i], av = ap[i], bv = bp[i];
        s += hv.x * av.x + hv.y * av.y + hv.z * av.z + hv.w * av.w;
        d += hv.x * bv.x + hv.y * bv.y + hv.z * bv.z + hv.w * bv.w;
        o[2 * i]     = __floats2half2_rn(hv.x, hv.y);
        o[2 * i + 1] = __floats2half2_rn(hv.z, hv.w);
    }
    g_es[idx] = s;
    g_ed[idx] = d;
}

// ---------------- GAT aggregation: warp per node, fp16 gather ----------------
// lane l owns features (2l,2l+1) of head a=l>>4 (slot0) and head a+2 (slot1).
// mode 0: out[N,128] = relu(agg + bias)  (concat); mode 1: out[N,32] = mean + bias
__global__ void gat_aggregate_kernel(const float* __restrict__ bias,
                                     float* __restrict__ outext, int outsel,
                                     int N, int mode) {
    float* out = pick(outsel, outext);
    const __half2* h2 = reinterpret_cast<const __half2*>(g_h16);
    int n = (blockIdx.x * blockDim.x + threadIdx.x) >> 5;
    int lane = threadIdx.x & 31;
    if (n >= N) return;
    int start = g_rowoff[n], end = g_rowoff[n + 1];
    float4 edn = reinterpret_cast<const float4*>(g_ed)[n];
    int a = lane >> 4;  // head of slot0 (slot1 = a+2)

    float acc0x = 0.f, acc0y = 0.f, acc1x = 0.f, acc1y = 0.f;
    float za = 0.f, za2 = 0.f;

    int i = start;
    for (; i + 1 < end; i += 2) {
        int s0 = g_csr[i], s1 = g_csr[i + 1];
        float4 e0 = reinterpret_cast<const float4*>(g_es)[s0];
        float4 e1 = reinterpret_cast<const float4*>(g_es)[s1];
        __half2 c00 = h2[(size_t)s0 * 64 + lane];
        __half2 c01 = h2[(size_t)s0 * 64 + 32 + lane];
        __half2 c10 = h2[(size_t)s1 * 64 + lane];
        __half2 c11 = h2[(size_t)s1 * 64 + 32 + lane];

        float w00 = __expf(lrelu(e0.x + edn.x));
        float w01 = __expf(lrelu(e0.y + edn.y));
        float w02 = __expf(lrelu(e0.z + edn.z));
        float w03 = __expf(lrelu(e0.w + edn.w));
        float w10 = __expf(lrelu(e1.x + edn.x));
        float w11 = __expf(lrelu(e1.y + edn.y));
        float w12 = __expf(lrelu(e1.z + edn.z));
        float w13 = __expf(lrelu(e1.w + edn.w));

        float wa0  = a ? w01 : w00, wa20 = a ? w03 : w02;
        float wa1  = a ? w11 : w10, wa21 = a ? w13 : w12;
        za  += wa0 + wa1;
        za2 += wa20 + wa21;

        float2 f00 = __half22float2(c00), f01 = __half22float2(c01);
        float2 f10 = __half22float2(c10), f11 = __half22float2(c11);
        acc0x += wa0 * f00.x + wa1 * f10.x;
        acc0y += wa0 * f00.y + wa1 * f10.y;
        acc1x += wa20 * f01.x + wa21 * f11.x;
        acc1y += wa20 * f01.y + wa21 * f11.y;
    }
    if (i < end) {
        int s0 = g_csr[i];
        float4 e0 = reinterpret_cast<const float4*>(g_es)[s0];
        __half2 c00 = h2[(size_t)s0 * 64 + lane];
        __half2 c01 = h2[(size_t)s0 * 64 + 32 + lane];
        float w00 = __expf(lrelu(e0.x + edn.x));
        float w01 = __expf(lrelu(e0.y + edn.y));
        float w02 = __expf(lrelu(e0.z + edn.z));
        float w03 = __expf(lrelu(e0.w + edn.w));
        float wa0 = a ? w01 : w00, wa20 = a ? w03 : w02;
        za += wa0; za2 += wa20;
        float2 f00 = __half22float2(c00), f01 = __half22float2(c01);
        acc0x += wa0 * f00.x; acc0y += wa0 * f00.y;
        acc1x += wa20 * f01.x; acc1y += wa20 * f01.y;
    }

    float ia  = 1.f / (za + 1e-16f);
    float ia2 = 1.f / (za2 + 1e-16f);

    if (mode == 0) {
        int f0 = 2 * lane;           // global concat feature of slot0
        float2 v0, v1;
        v0.x = fmaxf(acc0x * ia + bias[f0],          0.f);
        v0.y = fmaxf(acc0y * ia + bias[f0 + 1],      0.f);
        v1.x = fmaxf(acc1x * ia2 + bias[f0 + 64],    0.f);
        v1.y = fmaxf(acc1y * ia2 + bias[f0 + 65],    0.f);
        float2* op = reinterpret_cast<float2*>(out + (size_t)n * 128);
        op[lane]      = v0;
        op[lane + 32] = v1;
    } else {
        int f0 = (2 * lane) & 31;    // in-head feature
        float v0 = acc0x * ia + acc1x * ia2;
        float v1 = acc0y * ia + acc1y * ia2;
        v0 += __shfl_xor_sync(0xffffffffu, v0, 16);
        v1 += __shfl_xor_sync(0xffffffffu, v1, 16);
        out[(size_t)n * 32 + f0]     = 0.25f * v0 + bias[f0];
        out[(size_t)n * 32 + f0 + 1] = 0.25f * v1 + bias[f0 + 1];
    }
}

// ---------------- launch ----------------
extern "C" void kernel_launch(void* const* d_in, const int* in_sizes, int n_in,
                              void* d_out, int out_size) {
    const float* x   = (const float*)d_in[0];
    const void*  ei  = d_in[1];
    const float* W1  = (const float*)d_in[2];
    const float* a1s = (const float*)d_in[3];
    const float* a1d = (const float*)d_in[4];
    const float* b1  = (const float*)d_in[5];
    const float* W2  = (const float*)d_in[6];
    const float* a2s = (const float*)d_in[7];
    const float* a2d = (const float*)d_in[8];
    const float* b2  = (const float*)d_in[9];
    const float* M1w = (const float*)d_in[10];
    const float* M1b = (const float*)d_in[11];
    const float* g1  = (const float*)d_in[12];
    const float* be1 = (const float*)d_in[13];
    const float* M2w = (const float*)d_in[14];
    const float* M2b = (const float*)d_in[15];
    const float* g2  = (const float*)d_in[16];
    const float* be2 = (const float*)d_in[17];
    const float* W3  = (const float*)d_in[18];
    const float* a3s = (const float*)d_in[19];
    const float* a3d = (const float*)d_in[20];
    const float* b3  = (const float*)d_in[21];

    int N = in_sizes[0] / 128;
    if (N > N_MAX) N = N_MAX;
    int E = in_sizes[1] / 2;
    if (E > E_MAX) E = E_MAX;
    int ET = E + N;
    int nblk = (N + 255) / 256;

    dim3 t(256);
    dim3 gc((N + 127) / 128, 1);
    int sgrid = (4 * N + 255) / 256;
    int agrid = (N + 7) / 8;

    // prologue; layer-0 GEMM at launch #4 (profiled)
    zero_detect_kernel<<<nblk, 256>>>((const int*)ei, N);                    // 1
    build_edges_kernel<<<(ET + 255) / 256, 256>>>(ei, E, N);                 // 2
    scan_reduce_kernel<<<nblk, 256>>>(N);                                    // 3
    gemm_tc128_kernel<<<gc, t>>>(x, -1, W1, nullptr, -1, nullptr,
                                 nullptr, 0, N, 128, 0);                     // 4 (profiled)
    scan_block_kernel<<<1, 512>>>(nblk, g1, g2);                             // 5
    scan_final_kernel<<<nblk, 256>>>(N);                                     // 6
    scatter_kernel<<<(ET + 255) / 256, 256>>>(ET);                           // 7

    // layer 0 rest
    scores_kernel<<<sgrid, 256>>>(0, a1s, a1d, N);
    gat_aggregate_kernel<<<agrid, 256>>>(b1, nullptr, 1, N, 0);

    // MLP
    gemm_tc64_kernel<<<gc, t>>>(nullptr, 1, M1w, M1b, 0, be1, nullptr, 2, N, 128, 64, 1);
    gemm_tc128_kernel<<<gc, t>>>(nullptr, 2, M2w, M2b, 1, be2, nullptr, 0, N, 64, 1);

    // layer 1
    gemm_tc128_kernel<<<gc, t>>>(nullptr, 0, W2, nullptr, -1, nullptr, nullptr, 1, N, 128, 0);
    scores_kernel<<<sgrid, 256>>>(1, a2s, a2d, N);
    gat_aggregate_kernel<<<agrid, 256>>>(b2, nullptr, 0, N, 0);

    // output layer: mean over heads
    gemm_tc128_kernel<<<gc, t>>>(nullptr, 0, W3, nullptr, -1, nullptr, nullptr, 1, N, 128, 0);
    scores_kernel<<<sgrid, 256>>>(1, a3s, a3d, N);
    gat_aggregate_kernel<<<agrid, 256>>>(b3, (float*)d_out, -1, N, 1);
}

// round 11
// speedup vs baseline: 1.8730x; 1.8730x over previous
#include <cuda_runtime.h>
#include <cuda_fp16.h>

// ---------------- static scratch ----------------
#define N_MAX 50000
#define E_MAX 800000
#define ET_MAX (N_MAX + E_MAX)

__device__ __align__(16) float g_bufA[(size_t)N_MAX * 128];
__device__ __align__(16) float g_bufB[(size_t)N_MAX * 128];
__device__ __align__(16) float g_bufC[(size_t)N_MAX * 64];  // also aliased as edge-weight half4[ET]
__device__ __align__(16) float g_es[N_MAX * 4];
__device__ __align__(16) float g_ed[N_MAX * 4];
__device__ int   g_srcv[ET_MAX];
__device__ int   g_dstv[ET_MAX];
__device__ int   g_csr[ET_MAX];      // packed: src | dst<<16
__device__ int   g_cnt[N_MAX];
__device__ int   g_fill[N_MAX];
__device__ int   g_rowoff[N_MAX + 1];
__device__ int   g_blksum[512];
__device__ __align__(16) float g_sg1[64];
__device__ __align__(16) float g_sg2[128];
__device__ int   g_is64;

__device__ __forceinline__ float* pick(int sel, float* ext) {
    switch (sel) {
        case 0: return g_bufA;
        case 1: return g_bufB;
        case 2: return g_bufC;
        default: return ext;
    }
}

__device__ __forceinline__ const float* pick_scale(int sel) {
    switch (sel) {
        case 0: return g_sg1;
        case 1: return g_sg2;
        default: return nullptr;
    }
}

__device__ __forceinline__ float lrelu(float x) { return x > 0.f ? x : 0.2f * x; }

__device__ __forceinline__ unsigned f2tf32(float x) {
    unsigned u;
    asm("cvt.rna.tf32.f32 %0, %1;" : "=r"(u) : "f"(x));
    return u;
}

__device__ __forceinline__ void mma_tf32(float* d, const unsigned* a, const unsigned* b) {
    asm volatile(
        "mma.sync.aligned.m16n8k8.row.col.f32.tf32.tf32.f32 "
        "{%0,%1,%2,%3}, {%4,%5,%6,%7}, {%8,%9}, {%0,%1,%2,%3};\n"
        : "+f"(d[0]), "+f"(d[1]), "+f"(d[2]), "+f"(d[3])
        : "r"(a[0]), "r"(a[1]), "r"(a[2]), "r"(a[3]), "r"(b[0]), "r"(b[1]));
}

// ---------------- fused zero + dtype sniff ----------------
__global__ void zero_detect_kernel(const int* __restrict__ ei32, int N) {
    int i = blockIdx.x * blockDim.x + threadIdx.x;
    if (i < N) { g_cnt[i] = 0; g_fill[i] = 0; }
    if (blockIdx.x == 0 && threadIdx.x < 32) {
        int lane = threadIdx.x;
        int zeros = 0;
        for (int k = lane; k < 128; k += 32)
            if (ei32[2 * k + 1] == 0) zeros++;
        #pragma unroll
        for (int o = 16; o; o >>= 1) zeros += __shfl_xor_sync(0xffffffffu, zeros, o);
        if (lane == 0) g_is64 = (zeros > 64) ? 1 : 0;
    }
}

__global__ void build_edges_kernel(const void* __restrict__ ei, int E, int N) {
    int i = blockIdx.x * blockDim.x + threadIdx.x;
    int tot = E + N;
    if (i >= tot) return;
    int s, d;
    if (i < E) {
        if (g_is64) {
            const long long* p = (const long long*)ei;
            s = (int)p[i]; d = (int)p[(size_t)E + i];
        } else {
            const int* p = (const int*)ei;
            s = p[i]; d = p[E + i];
        }
        s = min(max(s, 0), N - 1);
        d = min(max(d, 0), N - 1);
    } else {
        s = i - E; d = s;
    }
    g_srcv[i] = s;
    g_dstv[i] = d;
    atomicAdd(&g_cnt[d], 1);
}

// ---------------- parallel 3-phase exclusive scan ----------------
__global__ void scan_reduce_kernel(int N) {
    __shared__ int ws[8];
    int b = blockIdx.x;
    int i = b * 256 + threadIdx.x;
    int v = (i < N) ? g_cnt[i] : 0;
    #pragma unroll
    for (int o = 16; o; o >>= 1) v += __shfl_xor_sync(0xffffffffu, v, o);
    int lane = threadIdx.x & 31, wid = threadIdx.x >> 5;
    if (lane == 0) ws[wid] = v;
    __syncthreads();
    if (threadIdx.x < 8) {
        int s = ws[threadIdx.x];
        #pragma unroll
        for (int o = 4; o; o >>= 1) s += __shfl_xor_sync(0xffu, s, o);
        if (threadIdx.x == 0) g_blksum[b] = s;
    }
}

__global__ void scan_block_kernel(int nblk, const float* __restrict__ ga,
                                  const float* __restrict__ gb) {
    __shared__ int wsum[16];
    int tid = threadIdx.x;
    int lane = tid & 31, wid = tid >> 5;
    int v = (tid < nblk) ? g_blksum[tid] : 0;
    int x = v;
    #pragma unroll
    for (int o = 1; o < 32; o <<= 1) {
        int y = __shfl_up_sync(0xffffffffu, x, o);
        if (lane >= o) x += y;
    }
    if (lane == 31) wsum[wid] = x;
    __syncthreads();
    if (tid < 16) {
        int ws = wsum[tid];
        int xs = ws;
        #pragma unroll
        for (int o = 1; o < 16; o <<= 1) {
            int y = __shfl_up_sync(0xffffu, xs, o);
            if (tid >= o) xs += y;
        }
        wsum[tid] = xs - ws;
    }
    __syncthreads();
    if (tid < nblk) g_blksum[tid] = wsum[wid] + x - v;
    float r = rsqrtf(1.0f + 1e-5f);
    if (tid < 64)  g_sg1[tid] = ga[tid] * r;
    if (tid < 128) g_sg2[tid] = gb[tid] * r;
}

__global__ void scan_final_kernel(int N) {
    __shared__ int wsum[8];
    int b = blockIdx.x;
    int tid = threadIdx.x;
    int lane = tid & 31, wid = tid >> 5;
    int i = b * 256 + tid;
    int v = (i < N) ? g_cnt[i] : 0;
    int x = v;
    #pragma unroll
    for (int o = 1; o < 32; o <<= 1) {
        int y = __shfl_up_sync(0xffffffffu, x, o);
        if (lane >= o) x += y;
    }
    if (lane == 31) wsum[wid] = x;
    __syncthreads();
    if (tid < 8) {
        int ws = wsum[tid];
        int xs = ws;
        #pragma unroll
        for (int o = 1; o < 8; o <<= 1) {
            int y = __shfl_up_sync(0xffu, xs, o);
            if (tid >= o) xs += y;
        }
        wsum[tid] = xs - ws;
    }
    __syncthreads();
    int excl = g_blksum[b] + wsum[wid] + x - v;
    if (i < N) g_rowoff[i] = excl;
    if (i == N - 1) g_rowoff[N] = excl + v;
}

// scatter packs src|dst<<16 (N < 65536 guaranteed by clamp)
__global__ void scatter_kernel(int ET) {
    int i = blockIdx.x * blockDim.x + threadIdx.x;
    if (i >= ET) return;
    int d = g_dstv[i];
    int pos = g_rowoff[d] + atomicAdd(&g_fill[d], 1);
    g_csr[pos] = g_srcv[i] | (d << 16);
}

// ---------------- tf32 tensor-core GEMM (tile 128x64, R7-proven) ----------------
__global__ void __launch_bounds__(256)
gemm_tc_kernel(const float* __restrict__ Aext, int Asel,
               const float* __restrict__ B,
               const float* __restrict__ bias,
               int ssel, const float* __restrict__ shift,
               float* __restrict__ Cext, int Csel,
               int N, int K, int M, int do_relu) {
    const float* A = pick(Asel, (float*)Aext);
    float* C = pick(Csel, Cext);
    const float* scale = pick_scale(ssel);

    __shared__ unsigned sA[128][36];
    __shared__ unsigned sB[32][68];

    int row0 = blockIdx.x * 128;
    int col0 = blockIdx.y * 64;
    int tid = threadIdx.x;
    int lane = tid & 31;
    int warp = tid >> 5;
    int wm = warp >> 1, wn = warp & 1;

    float acc[2][4][4];
    #pragma unroll
    for (int i = 0; i < 2; i++)
        #pragma unroll
        for (int j = 0; j < 4; j++)
            #pragma unroll
            for (int q = 0; q < 4; q++) acc[i][j][q] = 0.f;

    int ar[4], ac4[4];
    #pragma unroll
    for (int l = 0; l < 4; l++) {
        int fi = tid + l * 256;
        ar[l] = fi >> 3;
        ac4[l] = (fi & 7) << 2;
    }
    int bkr[2], bc4[2];
    #pragma unroll
    for (int l = 0; l < 2; l++) {
        int fi = tid + l * 256;
        bkr[l] = fi >> 4;
        bc4[l] = (fi & 15) << 2;
    }

    float4 pa[4], pb[2];
    #pragma unroll
    for (int l = 0; l < 4; l++) {
        pa[l] = make_float4(0.f, 0.f, 0.f, 0.f);
        if (row0 + ar[l] < N)
            pa[l] = *reinterpret_cast<const float4*>(A + (size_t)(row0 + ar[l]) * K + ac4[l]);
    }
    #pragma unroll
    for (int l = 0; l < 2; l++)
        pb[l] = *reinterpret_cast<const float4*>(B + (size_t)bkr[l] * M + col0 + bc4[l]);

    for (int k0 = 0; k0 < K; k0 += 32) {
        #pragma unroll
        for (int l = 0; l < 4; l++) {
            sA[ar[l]][ac4[l] + 0] = f2tf32(pa[l].x);
            sA[ar[l]][ac4[l] + 1] = f2tf32(pa[l].y);
            sA[ar[l]][ac4[l] + 2] = f2tf32(pa[l].z);
            sA[ar[l]][ac4[l] + 3] = f2tf32(pa[l].w);
        }
        #pragma unroll
        for (int l = 0; l < 2; l++) {
            sB[bkr[l]][bc4[l] + 0] = f2tf32(pb[l].x);
            sB[bkr[l]][bc4[l] + 1] = f2tf32(pb[l].y);
            sB[bkr[l]][bc4[l] + 2] = f2tf32(pb[l].z);
            sB[bkr[l]][bc4[l] + 3] = f2tf32(pb[l].w);
        }
        __syncthreads();

        int kn = k0 + 32;
        if (kn < K) {
            #pragma unroll
            for (int l = 0; l < 4; l++) {
                pa[l] = make_float4(0.f, 0.f, 0.f, 0.f);
                if (row0 + ar[l] < N)
                    pa[l] = *reinterpret_cast<const float4*>(A + (size_t)(row0 + ar[l]) * K + kn + ac4[l]);
            }
            #pragma unroll
            for (int l = 0; l < 2; l++)
                pb[l] = *reinterpret_cast<const float4*>(B + (size_t)(kn + bkr[l]) * M + col0 + bc4[l]);
        }

        #pragma unroll
        for (int ks = 0; ks < 4; ks++) {
            int kk = ks * 8;
            unsigned af[2][4];
            #pragma unroll
            for (int i = 0; i < 2; i++) {
                int r0 = wm * 32 + i * 16 + (lane >> 2);
                int c0 = kk + (lane & 3);
                af[i][0] = sA[r0][c0];
                af[i][1] = sA[r0 + 8][c0];
                af[i][2] = sA[r0][c0 + 4];
                af[i][3] = sA[r0 + 8][c0 + 4];
            }
            unsigned bf[4][2];
            #pragma unroll
            for (int j = 0; j < 4; j++) {
                int c = wn * 32 + j * 8 + (lane >> 2);
                int kr = kk + (lane & 3);
                bf[j][0] = sB[kr][c];
                bf[j][1] = sB[kr + 4][c];
            }
            #pragma unroll
            for (int i = 0; i < 2; i++)
                #pragma unroll
                for (int j = 0; j < 4; j++)
                    mma_tf32(acc[i][j], af[i], bf[j]);
        }
        __syncthreads();
    }

    #pragma unroll
    for (int i = 0; i < 2; i++) {
        int r0 = row0 + wm * 32 + i * 16 + (lane >> 2);
        #pragma unroll
        for (int j = 0; j < 4; j++) {
            int c0 = col0 + wn * 32 + j * 8 + ((lane & 3) << 1);
            #pragma unroll
            for (int q = 0; q < 4; q++) {
                int r = r0 + (q >> 1) * 8;
                int c = c0 + (q & 1);
                if (r >= N) continue;
                float v = acc[i][j][q];
                if (bias)  v += bias[c];
                if (do_relu) v = fmaxf(v, 0.f);
                if (scale) v = v * scale[c] + shift[c];
                C[(size_t)r * M + c] = v;
            }
        }
    }
}

// ---------------- attention scores ----------------
__global__ void scores_kernel(int hsel,
                              const float* __restrict__ as, const float* __restrict__ ad,
                              int N) {
    const float* h = pick(hsel, nullptr);
    int idx = blockIdx.x * blockDim.x + threadIdx.x;
    int n = idx >> 2, hh = idx & 3;
    if (n >= N) return;
    const float4* hp = reinterpret_cast<const float4*>(h + (size_t)n * 128 + hh * 32);
    const float4* ap = reinterpret_cast<const float4*>(as + hh * 32);
    const float4* bp = reinterpret_cast<const float4*>(ad + hh * 32);
    float s = 0.f, d = 0.f;
    #pragma unroll
    for (int i = 0; i < 8; i++) {
        float4 hv = hp[i], av = ap[i], bv = bp[i];
        s += hv.x * av.x + hv.y * av.y + hv.z * av.z + hv.w * av.w;
        d += hv.x * bv.x + hv.y * bv.y + hv.z * bv.z + hv.w * bv.w;
    }
    g_es[idx] = s;
    g_ed[idx] = d;
}

// ---------------- edge-parallel weight precompute ----------------
// w[pos][head] = exp(lrelu(es[src]+ed[dst])) stored as half4 in bufC alias.
__global__ void wcalc_kernel(int ET) {
    int i = blockIdx.x * blockDim.x + threadIdx.x;
    if (i >= ET) return;
    unsigned p = (unsigned)g_csr[i];
    int s = p & 0xffffu, d = p >> 16;
    float4 es4 = reinterpret_cast<const float4*>(g_es)[s];
    float4 ed4 = reinterpret_cast<const float4*>(g_ed)[d];
    float w0 = __expf(lrelu(es4.x + ed4.x));
    float w1 = __expf(lrelu(es4.y + ed4.y));
    float w2 = __expf(lrelu(es4.z + ed4.z));
    float w3 = __expf(lrelu(es4.w + ed4.w));
    __half2* ew = reinterpret_cast<__half2*>(g_bufC);
    ew[2 * i]     = __floats2half2_rn(w0, w1);
    ew[2 * i + 1] = __floats2half2_rn(w2, w3);
}

// ---------------- GAT aggregation: warp per node, float4 gather ----------------
// lane l owns feats (l&7)*4..+3 of head l>>3; one LDG.128 per edge per lane group.
__global__ void gat_aggregate_kernel(int hsel,
                                     const float* __restrict__ bias,
                                     float* __restrict__ outext, int outsel,
                                     int N, int mode) {
    const float* h = pick(hsel, nullptr);
    float* out = pick(outsel, outext);
    const __half2* ew = reinterpret_cast<const __half2*>(g_bufC);
    int n = (blockIdx.x * blockDim.x + threadIdx.x) >> 5;
    int lane = threadIdx.x & 31;
    if (n >= N) return;
    int start = g_rowoff[n], end = g_rowoff[n + 1];
    int hl = lane >> 3;

    float a0 = 0.f, a1 = 0.f, a2 = 0.f, a3 = 0.f, z = 0.f;

    int i = start;
    for (; i + 1 < end; i += 2) {
        unsigned p0 = (unsigned)g_csr[i], p1 = (unsigned)g_csr[i + 1];
        __half2 wa0 = ew[2 * i],     wb0 = ew[2 * i + 1];
        __half2 wa1 = ew[2 * i + 2], wb1 = ew[2 * i + 3];
        int s0 = p0 & 0xffffu, s1 = p1 & 0xffffu;
        float4 h0 = *reinterpret_cast<const float4*>(h + (size_t)s0 * 128 + lane * 4);
        float4 h1 = *reinterpret_cast<const float4*>(h + (size_t)s1 * 128 + lane * 4);
        float2 l0 = __half22float2(wa0), m0 = __half22float2(wb0);
        float2 l1 = __half22float2(wa1), m1 = __half22float2(wb1);
        float w0 = (hl == 0) ? l0.x : (hl == 1) ? l0.y : (hl == 2) ? m0.x : m0.y;
        float w1 = (hl == 0) ? l1.x : (hl == 1) ? l1.y : (hl == 2) ? m1.x : m1.y;
        z  += w0 + w1;
        a0 += w0 * h0.x + w1 * h1.x;
        a1 += w0 * h0.y + w1 * h1.y;
        a2 += w0 * h0.z + w1 * h1.z;
        a3 += w0 * h0.w + w1 * h1.w;
    }
    if (i < end) {
        unsigned p0 = (unsigned)g_csr[i];
        __half2 wa0 = ew[2 * i], wb0 = ew[2 * i + 1];
        int s0 = p0 & 0xffffu;
        float4 h0 = *reinterpret_cast<const float4*>(h + (size_t)s0 * 128 + lane * 4);
        float2 l0 = __half22float2(wa0), m0 = __half22float2(wb0);
        float w0 = (hl == 0) ? l0.x : (hl == 1) ? l0.y : (hl == 2) ? m0.x : m0.y;
        z  += w0;
        a0 += w0 * h0.x;
        a1 += w0 * h0.y;
        a2 += w0 * h0.z;
        a3 += w0 * h0.w;
    }

    float iz = 1.f / (z + 1e-16f);
    float v0 = a0 * iz, v1 = a1 * iz, v2 = a2 * iz, v3 = a3 * iz;

    if (mode == 0) {
        int f = lane * 4;   // global concat feature = (l>>3)*32 + (l&7)*4
        float4 v;
        v.x = fmaxf(v0 + bias[f],     0.f);
        v.y = fmaxf(v1 + bias[f + 1], 0.f);
        v.z = fmaxf(v2 + bias[f + 2], 0.f);
        v.w = fmaxf(v3 + bias[f + 3], 0.f);
        reinterpret_cast<float4*>(out + (size_t)n * 128)[lane] = v;
    } else {
        // mean over heads: sum lanes with same (l&7) across the 4 head groups
        v0 += __shfl_xor_sync(0xffffffffu, v0, 8);
        v1 += __shfl_xor_sync(0xffffffffu, v1, 8);
        v2 += __shfl_xor_sync(0xffffffffu, v2, 8);
        v3 += __shfl_xor_sync(0xffffffffu, v3, 8);
        v0 += __shfl_xor_sync(0xffffffffu, v0, 16);
        v1 += __shfl_xor_sync(0xffffffffu, v1, 16);
        v2 += __shfl_xor_sync(0xffffffffu, v2, 16);
        v3 += __shfl_xor_sync(0xffffffffu, v3, 16);
        if (lane < 8) {
            int f = lane * 4;
            float4 v;
            v.x = 0.25f * v0 + bias[f];
            v.y = 0.25f * v1 + bias[f + 1];
            v.z = 0.25f * v2 + bias[f + 2];
            v.w = 0.25f * v3 + bias[f + 3];
            reinterpret_cast<float4*>(out + (size_t)n * 32)[lane] = v;
        }
    }
}

// ---------------- launch ----------------
extern "C" void kernel_launch(void* const* d_in, const int* in_sizes, int n_in,
                              void* d_out, int out_size) {
    const float* x   = (const float*)d_in[0];
    const void*  ei  = d_in[1];
    const float* W1  = (const float*)d_in[2];
    const float* a1s = (const float*)d_in[3];
    const float* a1d = (const float*)d_in[4];
    const float* b1  = (const float*)d_in[5];
    const float* W2  = (const float*)d_in[6];
    const float* a2s = (const float*)d_in[7];
    const float* a2d = (const float*)d_in[8];
    const float* b2  = (const float*)d_in[9];
    const float* M1w = (const float*)d_in[10];
    const float* M1b = (const float*)d_in[11];
    const float* g1  = (const float*)d_in[12];
    const float* be1 = (const float*)d_in[13];
    const float* M2w = (const float*)d_in[14];
    const float* M2b = (const float*)d_in[15];
    const float* g2  = (const float*)d_in[16];
    const float* be2 = (const float*)d_in[17];
    const float* W3  = (const float*)d_in[18];
    const float* a3s = (const float*)d_in[19];
    const float* a3d = (const float*)d_in[20];
    const float* b3  = (const float*)d_in[21];

    int N = in_sizes[0] / 128;
    if (N > N_MAX) N = N_MAX;
    int E = in_sizes[1] / 2;
    if (E > E_MAX) E = E_MAX;
    int ET = E + N;
    int nblk = (N + 255) / 256;
    int eblk = (ET + 255) / 256;

    dim3 t(256);
    dim3 g128((N + 127) / 128, 2);
    dim3 g64((N + 127) / 128, 1);
    int sgrid = (4 * N + 255) / 256;
    int agrid = (N + 7) / 8;

    // prologue; layer-0 GEMM at launch #4 (profiled)
    zero_detect_kernel<<<nblk, 256>>>((const int*)ei, N);                    // 1
    build_edges_kernel<<<eblk, 256>>>(ei, E, N);                             // 2
    scan_reduce_kernel<<<nblk, 256>>>(N);                                    // 3
    gemm_tc_kernel<<<g128, t>>>(x, -1, W1, nullptr, -1, nullptr,
                                nullptr, 0, N, 128, 128, 0);                 // 4 (profiled)
    scan_block_kernel<<<1, 512>>>(nblk, g1, g2);                             // 5
    scan_final_kernel<<<nblk, 256>>>(N);                                     // 6
    scatter_kernel<<<eblk, 256>>>(ET);                                       // 7

    // layer 0
    scores_kernel<<<sgrid, 256>>>(0, a1s, a1d, N);
    wcalc_kernel<<<eblk, 256>>>(ET);
    gat_aggregate_kernel<<<agrid, 256>>>(0, b1, nullptr, 1, N, 0);

    // MLP (bufC becomes MLP hidden; edge weights dead by now)
    gemm_tc_kernel<<<g64, t>>>(nullptr, 1, M1w, M1b, 0, be1, nullptr, 2, N, 128, 64, 1);
    gemm_tc_kernel<<<g128, t>>>(nullptr, 2, M2w, M2b, 1, be2, nullptr, 0, N, 64, 128, 1);

    // layer 1
    gemm_tc_kernel<<<g128, t>>>(nullptr, 0, W2, nullptr, -1, nullptr, nullptr, 1, N, 128, 128, 0);
    scores_kernel<<<sgrid, 256>>>(1, a2s, a2d, N);
    wcalc_kernel<<<eblk, 256>>>(ET);
    gat_aggregate_kernel<<<agrid, 256>>>(1, b2, nullptr, 0, N, 0);

    // output layer: mean over heads
    gemm_tc_kernel<<<g128, t>>>(nullptr, 0, W3, nullptr, -1, nullptr, nullptr, 1, N, 128, 128, 0);
    scores_kernel<<<sgrid, 256>>>(1, a3s, a3d, N);
    wcalc_kernel<<<eblk, 256>>>(ET);
    gat_aggregate_kernel<<<agrid, 256>>>(1, b3, (float*)d_out, -1, N, 1);
}